// round 1
// baseline (speedup 1.0000x reference)
#include <cuda_runtime.h>
#include <math.h>

#define FNUM   20
#define NPAIR  190          // 20*19/2
#define VTOT   1000000      // sum of field dims
#define ED     16
#define FIELDW 50000
#define WPB    8            // warps per block

__global__ __launch_bounds__(256, 4)
void ffm_kernel(const int* __restrict__ x,
                const float* __restrict__ Wl,
                const float* __restrict__ Wc,
                const float* __restrict__ bias,
                float* __restrict__ out, int B)
{
    __shared__ int sx[WPB][FNUM];
    __shared__ unsigned char pi[NPAIR], pj[NPAIR];

    int tid = threadIdx.x;
    if (tid == 0) {
        int p = 0;
        for (int i = 0; i < FNUM; i++)
            for (int j = i + 1; j < FNUM; j++) { pi[p] = (unsigned char)i; pj[p] = (unsigned char)j; p++; }
    }

    int w      = tid >> 5;
    int lane   = tid & 31;
    int sample = blockIdx.x * WPB + w;

    if (lane < FNUM && sample < B)
        sx[w][lane] = x[sample * FNUM + lane] + lane * FIELDW;
    __syncthreads();
    if (sample >= B) return;

    float acc = 0.f;
    // linear term: lanes 0..19 each fetch one W_linear entry
    if (lane < FNUM)
        acc = Wl[sx[w][lane]];

    const int quad = lane >> 2;        // 0..7  : which pair in this iteration
    const int kc   = (lane & 3) * 4;   // 0,4,8,12 : embed-dim chunk

    #pragma unroll 4
    for (int it = 0; it < 24; it++) {
        int p = it * 8 + quad;
        if (p < NPAIR) {
            int i  = pi[p];
            int j  = pj[p];
            long xi = sx[w][i];
            long xj = sx[w][j];
            // a = W_cross[j, xo_i, kc..kc+3], b = W_cross[i, xo_j, kc..kc+3]
            const float4 a = *(const float4*)(Wc + ((long)j * VTOT + xi) * ED + kc);
            const float4 b = *(const float4*)(Wc + ((long)i * VTOT + xj) * ED + kc);
            acc += a.x * b.x + a.y * b.y + a.z * b.z + a.w * b.w;
        }
    }

    // warp tree-reduce
    #pragma unroll
    for (int s = 16; s; s >>= 1)
        acc += __shfl_xor_sync(0xffffffffu, acc, s);

    if (lane == 0) {
        float z = acc + bias[0];
        out[sample] = 1.f / (1.f + __expf(-z));
    }
}

extern "C" void kernel_launch(void* const* d_in, const int* in_sizes, int n_in,
                              void* d_out, int out_size)
{
    const int*   x  = (const int*)  d_in[0];
    const float* Wl = (const float*)d_in[1];
    const float* Wc = (const float*)d_in[2];
    const float* bs = (const float*)d_in[3];
    float* out = (float*)d_out;

    int B = in_sizes[0] / FNUM;
    int blocks = (B + WPB - 1) / WPB;
    ffm_kernel<<<blocks, 256>>>(x, Wl, Wc, bs, out, B);
}